// round 2
// baseline (speedup 1.0000x reference)
#include <cuda_runtime.h>
#include <math.h>

#define BATCH 256
#define NNODE 512
#define FEAT  128
#define NE    4

// Scratch: h[b][e][m][u] for e in 0..3, plus slot e=4 = n @ W2 + b2.
// 256 * 5 * 512 * 128 floats = 335 MB (static device alloc, allowed).
__device__ float g_h[(size_t)BATCH * 5 * NNODE * FEAT];

// ---------------------------------------------------------------------------
// Kernel 1: H[b][e][m][u] = n[b,m,:] @ W_e + bias_e   (e = 0..4, e==4 -> W2/b2)
// Block: 256 threads computes a 128(rows) x 128(u) tile. K = 128.
// ---------------------------------------------------------------------------
__global__ __launch_bounds__(256) void k1_linears(
    const float* __restrict__ nt,
    const float* __restrict__ Wadj,
    const float* __restrict__ badj,
    const float* __restrict__ W2,
    const float* __restrict__ b2)
{
    const int e    = blockIdx.y;                 // 0..4
    const int row0 = blockIdx.x * 128;           // global row in [0, B*N)
    const float* __restrict__ W    = (e < NE) ? (Wadj + (size_t)e * FEAT * FEAT) : W2;
    const float* __restrict__ bias = (e < NE) ? (badj + e * FEAT) : b2;

    __shared__ float As[16][128];   // As[k][row]
    __shared__ float Bs[16][128];   // Bs[k][u]

    const int t  = threadIdx.x;     // 0..255
    const int tr = t >> 4;          // 0..15 -> rows tr*8..tr*8+7
    const int tc = t & 15;          // 0..15 -> cols tc*8..tc*8+7

    float acc[8][8];
    #pragma unroll
    for (int i = 0; i < 8; i++)
        #pragma unroll
        for (int j = 0; j < 8; j++) acc[i][j] = 0.f;

    #pragma unroll 1
    for (int k0 = 0; k0 < FEAT; k0 += 16) {
        // load A tile: 128 rows x 16 k  (2048 elems / 256 thr = 8 each)
        #pragma unroll
        for (int j = 0; j < 8; j++) {
            int ei = t + j * 256;
            int i  = ei >> 4, kk = ei & 15;
            As[kk][i] = nt[(size_t)(row0 + i) * FEAT + k0 + kk];
        }
        // load B tile: 16 k x 128 u (2048 elems / 256 thr = 8 each)
        #pragma unroll
        for (int j = 0; j < 8; j++) {
            int ei = t + j * 256;
            int kk = ei >> 7, u = ei & 127;
            Bs[kk][u] = W[(size_t)(k0 + kk) * FEAT + u];
        }
        __syncthreads();

        #pragma unroll
        for (int kk = 0; kk < 16; kk++) {
            float a[8], b[8];
            #pragma unroll
            for (int j = 0; j < 8; j++) a[j] = As[kk][tr * 8 + j];
            #pragma unroll
            for (int j = 0; j < 8; j++) b[j] = Bs[kk][tc * 8 + j];
            #pragma unroll
            for (int i = 0; i < 8; i++)
                #pragma unroll
                for (int j = 0; j < 8; j++)
                    acc[i][j] = fmaf(a[i], b[j], acc[i][j]);
        }
        __syncthreads();
    }

    // epilogue: add bias, scatter to g_h[b][e][m][u]
    #pragma unroll
    for (int i = 0; i < 8; i++) {
        int r = row0 + tr * 8 + i;
        int b = r >> 9;           // / 512
        int m = r & 511;
        float* dst = g_h + (((size_t)b * 5 + e) * NNODE + m) * FEAT + tc * 8;
        #pragma unroll
        for (int j = 0; j < 8; j++)
            dst[j] = acc[i][j] + bias[tc * 8 + j];
    }
}

// ---------------------------------------------------------------------------
// Kernel 2: out[b,n,u] = tanh( sum_e adj[b,e,n,:] @ H[b,e,:,u] + H[b,4,n,u] )
// Block: 256 threads computes 128(rows) x 128(u). K = 4 * 512 = 2048.
// Grid: 256 batches * 4 row tiles = 1024 blocks.
// ---------------------------------------------------------------------------
__global__ __launch_bounds__(256) void k2_msgpass(
    const float* __restrict__ adj,
    float* __restrict__ out)
{
    const int b    = blockIdx.x >> 2;
    const int row0 = (blockIdx.x & 3) * 128;

    __shared__ float As[16][128];   // As[k][row]  (adj slice)
    __shared__ float Bs[16][128];   // Bs[k][u]    (h slice)

    const int t  = threadIdx.x;
    const int tr = t >> 4;
    const int tc = t & 15;

    float acc[8][8];
    #pragma unroll
    for (int i = 0; i < 8; i++)
        #pragma unroll
        for (int j = 0; j < 8; j++) acc[i][j] = 0.f;

    #pragma unroll 1
    for (int e = 0; e < NE; e++) {
        const float* __restrict__ A  = adj + ((size_t)(b * NE + e) * NNODE + row0) * NNODE;
        const float* __restrict__ Bm = g_h + ((size_t)b * 5 + e) * NNODE * FEAT;

        #pragma unroll 1
        for (int k0 = 0; k0 < NNODE; k0 += 16) {
            #pragma unroll
            for (int j = 0; j < 8; j++) {
                int ei = t + j * 256;
                int i  = ei >> 4, kk = ei & 15;
                As[kk][i] = A[(size_t)i * NNODE + k0 + kk];
            }
            #pragma unroll
            for (int j = 0; j < 8; j++) {
                int ei = t + j * 256;
                int kk = ei >> 7, u = ei & 127;
                Bs[kk][u] = Bm[(size_t)(k0 + kk) * FEAT + u];
            }
            __syncthreads();

            #pragma unroll
            for (int kk = 0; kk < 16; kk++) {
                float a[8], bb[8];
                #pragma unroll
                for (int j = 0; j < 8; j++) a[j]  = As[kk][tr * 8 + j];
                #pragma unroll
                for (int j = 0; j < 8; j++) bb[j] = Bs[kk][tc * 8 + j];
                #pragma unroll
                for (int i = 0; i < 8; i++)
                    #pragma unroll
                    for (int j = 0; j < 8; j++)
                        acc[i][j] = fmaf(a[i], bb[j], acc[i][j]);
            }
            __syncthreads();
        }
    }

    // epilogue: + lin2 (slot e=4), tanh, store
    const float* __restrict__ lin2 =
        g_h + (((size_t)b * 5 + 4) * NNODE + row0) * FEAT;

    #pragma unroll
    for (int i = 0; i < 8; i++) {
        const int r  = row0 + tr * 8 + i;
        const float* l2row = lin2 + (size_t)(tr * 8 + i) * FEAT + tc * 8;
        float* orow = out + ((size_t)(b * NNODE + r)) * FEAT + tc * 8;
        #pragma unroll
        for (int j = 0; j < 8; j++)
            orow[j] = tanhf(acc[i][j] + l2row[j]);
    }
}

extern "C" void kernel_launch(void* const* d_in, const int* in_sizes, int n_in,
                              void* d_out, int out_size)
{
    const float* n_tensor   = (const float*)d_in[0];
    const float* adj_tensor = (const float*)d_in[1];
    const float* W_adj      = (const float*)d_in[2];
    const float* b_adj      = (const float*)d_in[3];
    const float* W2         = (const float*)d_in[4];
    const float* b2         = (const float*)d_in[5];
    float* out = (float*)d_out;

    // Kernel 1: (B*N/128) row tiles x 5 weight slots
    dim3 g1((BATCH * NNODE) / 128, 5);
    k1_linears<<<g1, 256>>>(n_tensor, W_adj, b_adj, W2, b2);

    // Kernel 2: 256 batches x 4 row tiles
    k2_msgpass<<<BATCH * 4, 256>>>(adj_tensor, out);
}

// round 4
// speedup vs baseline: 2.0459x; 2.0459x over previous
#include <cuda_runtime.h>
#include <cuda_bf16.h>
#include <cstdint>
#include <math.h>

#define BATCH 256
#define NNODE 512
#define FEAT  128
#define NE    4

// ---------------- scratch (static device allocs allowed) ----------------
__device__ __nv_bfloat16 g_wth[5 * FEAT * FEAT];                  // W^T hi [e][u][k]
__device__ __nv_bfloat16 g_wtl[5 * FEAT * FEAT];                  // W^T lo
__device__ __nv_bfloat16 g_hh[(size_t)BATCH * NE * FEAT * NNODE]; // h hi [b][e][u][m]
__device__ __nv_bfloat16 g_hl[(size_t)BATCH * NE * FEAT * NNODE]; // h lo
__device__ float         g_l2[(size_t)BATCH * NNODE * FEAT];      // n@W2+b2 [row][u]

// ---------------- helpers ----------------
__device__ __forceinline__ uint32_t smem_u32(const void* p) {
    uint32_t a;
    asm("{ .reg .u64 t; cvta.to.shared.u64 t, %1; cvt.u32.u64 %0, t; }" : "=r"(a) : "l"(p));
    return a;
}
// SW128-style swizzle on a linear byte offset (rows of 128B): 16B-chunk ^= row%8
#define SWZ(x) ((x) ^ (((x) >> 3) & 0x70))

__device__ __forceinline__ void split2(float a, float b, uint32_t& hh, uint32_t& ll) {
    __nv_bfloat162 h = __floats2bfloat162_rn(a, b);
    float ra = a - __low2float(h);
    float rb = b - __high2float(h);
    hh = *reinterpret_cast<uint32_t*>(&h);
    __nv_bfloat162 l = __floats2bfloat162_rn(ra, rb);
    ll = *reinterpret_cast<uint32_t*>(&l);
}

__device__ __forceinline__ void ldm4(uint32_t a[4], uint32_t adr) {
    asm volatile("ldmatrix.sync.aligned.m8n8.x4.shared.b16 {%0,%1,%2,%3}, [%4];"
        : "=r"(a[0]), "=r"(a[1]), "=r"(a[2]), "=r"(a[3]) : "r"(adr));
}
__device__ __forceinline__ void ldm2(uint32_t b[2], uint32_t adr) {
    asm volatile("ldmatrix.sync.aligned.m8n8.x2.shared.b16 {%0,%1}, [%2];"
        : "=r"(b[0]), "=r"(b[1]) : "r"(adr));
}
__device__ __forceinline__ void mma_bf(float c[4], const uint32_t a[4], const uint32_t b[2]) {
    asm volatile("mma.sync.aligned.m16n8k16.row.col.f32.bf16.bf16.f32 "
        "{%0,%1,%2,%3}, {%4,%5,%6,%7}, {%8,%9}, {%0,%1,%2,%3};"
        : "+f"(c[0]), "+f"(c[1]), "+f"(c[2]), "+f"(c[3])
        : "r"(a[0]), "r"(a[1]), "r"(a[2]), "r"(a[3]), "r"(b[0]), "r"(b[1]));
}
#define CP_COMMIT() asm volatile("cp.async.commit_group;" ::: "memory")
#define CP_WAIT0()  asm volatile("cp.async.wait_group 0;" ::: "memory")

// ---- tile: 128 rows x 128B; per row: [hi: 32 bf16 | lo: 32 bf16], swizzled ----

// A loader (fp32 -> split) into registers for pipelining. 16 values/thread.
struct AR { uint32_t h[8], l[8]; };
__device__ __forceinline__ void loadA_regs(AR& a, const float* __restrict__ g, int rs, int t) {
    int r = t >> 1, c0 = (t & 1) * 16;
    const float* src = g + (size_t)r * rs + c0;
    #pragma unroll
    for (int j = 0; j < 4; j++) {
        float4 v = *reinterpret_cast<const float4*>(src + 4 * j);
        split2(v.x, v.y, a.h[2 * j], a.l[2 * j]);
        split2(v.z, v.w, a.h[2 * j + 1], a.l[2 * j + 1]);
    }
}
__device__ __forceinline__ void storeA_regs(const AR& a, char* sm, int base, int t) {
    int r = t >> 1, c0 = (t & 1) * 16;
    #pragma unroll
    for (int j = 0; j < 4; j++) {
        int col = c0 + 4 * j;
        *reinterpret_cast<uint2*>(sm + base + SWZ(r * 128 + col * 2)) =
            make_uint2(a.h[2 * j], a.h[2 * j + 1]);
        *reinterpret_cast<uint2*>(sm + base + SWZ(r * 128 + 64 + col * 2)) =
            make_uint2(a.l[2 * j], a.l[2 * j + 1]);
    }
}
// direct (non-pipelined) fp32 split load
__device__ __forceinline__ void loadA_f32(char* sm, int base, const float* __restrict__ g,
                                          int rs, int t) {
    AR a;
    loadA_regs(a, g, rs, t);
    storeA_regs(a, sm, base, t);
}
// B loader: bf16 hi/lo planes (128 rows x 32 k) via cp.async. 1024 x 16B chunks.
__device__ __forceinline__ void loadB_async(uint32_t sb, int base,
                                            const __nv_bfloat16* __restrict__ gh,
                                            const __nv_bfloat16* __restrict__ gl,
                                            int rs, int t) {
    #pragma unroll
    for (int j = 0; j < 4; j++) {
        int c = t + 256 * j;
        int p = c >> 9, r = (c >> 2) & 127, q = c & 3;
        const __nv_bfloat16* src = (p ? gl : gh) + (size_t)r * rs + q * 8;
        uint32_t dst = sb + base + SWZ(r * 128 + p * 64 + q * 16);
        asm volatile("cp.async.cg.shared.global [%0], [%1], 16;" :: "r"(dst), "l"(src) : "memory");
    }
}

// compute one 32-k stage: 2 k16-steps x (2m x 8n) x 3 split-products
__device__ __forceinline__ void compute_stage(uint32_t sb, int offA, int offB,
                                              int wm, int wn, int lane,
                                              float acc[2][8][4]) {
    #pragma unroll
    for (int ks = 0; ks < 2; ks++) {
        int k0 = ks * 16;
        uint32_t Ah[2][4], Al[2][4];
        #pragma unroll
        for (int mf = 0; mf < 2; mf++) {
            int row = wm * 32 + mf * 16 + (lane & 15);
            int kk  = k0 + ((lane >> 4) * 8);
            ldm4(Ah[mf], sb + offA + SWZ(row * 128 + kk * 2));
            ldm4(Al[mf], sb + offA + SWZ(row * 128 + 64 + kk * 2));
        }
        #pragma unroll
        for (int nf = 0; nf < 8; nf++) {
            int u  = wn * 64 + nf * 8 + (lane & 7);
            int kk = k0 + (((lane >> 3) & 1) * 8);
            uint32_t Bh[2], Bl[2];
            ldm2(Bh, sb + offB + SWZ(u * 128 + kk * 2));
            ldm2(Bl, sb + offB + SWZ(u * 128 + 64 + kk * 2));
            mma_bf(acc[0][nf], Ah[0], Bh);
            mma_bf(acc[1][nf], Ah[1], Bh);
            mma_bf(acc[0][nf], Ah[0], Bl);
            mma_bf(acc[1][nf], Ah[1], Bl);
            mma_bf(acc[0][nf], Al[0], Bh);
            mma_bf(acc[1][nf], Al[1], Bh);
        }
    }
}

// ---------------- pre-kernel: transpose+split W ----------------
__global__ __launch_bounds__(256) void k_split_w(const float* __restrict__ Wadj,
                                                 const float* __restrict__ W2) {
    int e = blockIdx.x;
    const float* W = (e < NE) ? (Wadj + (size_t)e * FEAT * FEAT) : W2;
    for (int idx = threadIdx.x; idx < FEAT * FEAT; idx += 256) {
        int k = idx >> 7, u = idx & 127;
        float v = W[idx];
        __nv_bfloat16 h = __float2bfloat16(v);
        float r = v - __bfloat162float(h);
        g_wth[((size_t)e * FEAT + u) * FEAT + k] = h;
        g_wtl[((size_t)e * FEAT + u) * FEAT + k] = __float2bfloat16(r);
    }
}

// ---------------- k_lin: h_e = n @ W_e + b_e (HMMA split-bf16) ----------------
// smem: A sub-tiles 0..3 at st*16384, B sub-tiles at 65536 + st*16384. 128KB.
#define LIN_SMEM 131072
__global__ __launch_bounds__(256) void k_lin(const float* __restrict__ nt,
                                             const float* __restrict__ badj,
                                             const float* __restrict__ b2) {
    extern __shared__ char sm[];
    uint32_t sb = smem_u32(sm);
    int t = threadIdx.x, lane = t & 31, w = t >> 5;
    int wm = w >> 1, wn = w & 1;
    int r0 = blockIdx.x * 128, e = blockIdx.y;

    const __nv_bfloat16* wh = g_wth + (size_t)e * FEAT * FEAT;
    const __nv_bfloat16* wl = g_wtl + (size_t)e * FEAT * FEAT;
    #pragma unroll
    for (int st = 0; st < 4; st++)
        loadB_async(sb, 65536 + st * 16384, wh + st * 32, wl + st * 32, FEAT, t);
    CP_COMMIT();
    #pragma unroll
    for (int st = 0; st < 4; st++)
        loadA_f32(sm, st * 16384, nt + (size_t)r0 * FEAT + st * 32, FEAT, t);
    CP_WAIT0();
    __syncthreads();

    float acc[2][8][4];
    #pragma unroll
    for (int i = 0; i < 2; i++)
        #pragma unroll
        for (int j = 0; j < 8; j++)
            #pragma unroll
            for (int q = 0; q < 4; q++) acc[i][j][q] = 0.f;

    #pragma unroll
    for (int st = 0; st < 4; st++)
        compute_stage(sb, st * 16384, 65536 + st * 16384, wm, wn, lane, acc);

    const float* bias = (e < NE) ? (badj + e * FEAT) : b2;

    if (e == NE) {
        // lin2: direct fp32 store with bias
        #pragma unroll
        for (int mf = 0; mf < 2; mf++)
            #pragma unroll
            for (int nf = 0; nf < 8; nf++) {
                int r = wm * 32 + mf * 16 + (lane >> 2);
                int c = wn * 64 + nf * 8 + 2 * (lane & 3);
                float2 bv = *reinterpret_cast<const float2*>(bias + c);
                size_t g0 = (size_t)(r0 + r) * FEAT + c;
                *reinterpret_cast<float2*>(g_l2 + g0) =
                    make_float2(acc[mf][nf][0] + bv.x, acc[mf][nf][1] + bv.y);
                size_t g1 = g0 + (size_t)8 * FEAT;
                *reinterpret_cast<float2*>(g_l2 + g1) =
                    make_float2(acc[mf][nf][2] + bv.x, acc[mf][nf][3] + bv.y);
            }
    } else {
        // stage to smem then transposed hi/lo store
        __syncthreads();                 // everyone done reading tiles
        float* stg = reinterpret_cast<float*>(sm);   // [128][132]
        #pragma unroll
        for (int mf = 0; mf < 2; mf++)
            #pragma unroll
            for (int nf = 0; nf < 8; nf++) {
                int r = wm * 32 + mf * 16 + (lane >> 2);
                int c = wn * 64 + nf * 8 + 2 * (lane & 3);
                float2 bv = *reinterpret_cast<const float2*>(bias + c);
                stg[r * 132 + c]           = acc[mf][nf][0] + bv.x;
                stg[r * 132 + c + 1]       = acc[mf][nf][1] + bv.y;
                stg[(r + 8) * 132 + c]     = acc[mf][nf][2] + bv.x;
                stg[(r + 8) * 132 + c + 1] = acc[mf][nf][3] + bv.y;
            }
        __syncthreads();

        int b = r0 >> 9, m0 = r0 & 511;
        int u = t >> 1, mh = (t & 1) * 64;
        size_t base = (((size_t)(b * NE + e) * FEAT) + u) * NNODE + m0 + mh;
        #pragma unroll 4
        for (int j = 0; j < 64; j += 4) {
            float v0 = stg[(mh + j + 0) * 132 + u];
            float v1 = stg[(mh + j + 1) * 132 + u];
            float v2 = stg[(mh + j + 2) * 132 + u];
            float v3 = stg[(mh + j + 3) * 132 + u];
            uint32_t h0, l0, h1, l1;
            split2(v0, v1, h0, l0);
            split2(v2, v3, h1, l1);
            *reinterpret_cast<uint2*>(&g_hh[base + j]) = make_uint2(h0, h1);
            *reinterpret_cast<uint2*>(&g_hl[base + j]) = make_uint2(l0, l1);
        }
    }
}

// ---------------- k_mp: out = tanh(sum_e adj_e @ h_e + lin2) ----------------
// smem: A buf s at s*16384; B buf s at 32768 + s*16384. 64KB.
#define MP_SMEM 65536
__global__ __launch_bounds__(256) void k_mp(const float* __restrict__ adj,
                                            float* __restrict__ out) {
    extern __shared__ char sm[];
    uint32_t sb = smem_u32(sm);
    int t = threadIdx.x, lane = t & 31, w = t >> 5;
    int wm = w >> 1, wn = w & 1;
    int b = blockIdx.x >> 2, n0 = (blockIdx.x & 3) * 128;

    float acc[2][8][4];
    #pragma unroll
    for (int i = 0; i < 2; i++)
        #pragma unroll
        for (int j = 0; j < 8; j++)
            #pragma unroll
            for (int q = 0; q < 4; q++) acc[i][j][q] = 0.f;

    AR ar;
    // chunk i (0..63): e = i>>4, k0 = (i&15)*32
    {
        const float* Ap = adj + ((size_t)(b * NE + 0) * NNODE + n0) * NNODE;
        loadA_regs(ar, Ap, NNODE, t);
        size_t hb = ((size_t)(b * NE + 0) * FEAT) * NNODE;
        loadB_async(sb, 32768, g_hh + hb, g_hl + hb, NNODE, t);
        CP_COMMIT();
        storeA_regs(ar, sm, 0, t);
        CP_WAIT0();
        __syncthreads();
    }

    #pragma unroll 1
    for (int i = 0; i < 64; i++) {
        int s = i & 1;
        if (i < 63) {
            int e = (i + 1) >> 4, k0 = ((i + 1) & 15) * 32;
            const float* Ap = adj + ((size_t)(b * NE + e) * NNODE + n0) * NNODE + k0;
            loadA_regs(ar, Ap, NNODE, t);
            size_t hb = ((size_t)(b * NE + e) * FEAT) * NNODE + k0;
            loadB_async(sb, 32768 + (s ^ 1) * 16384, g_hh + hb, g_hl + hb, NNODE, t);
            CP_COMMIT();
        }
        compute_stage(sb, s * 16384, 32768 + s * 16384, wm, wn, lane, acc);
        if (i < 63) {
            __syncthreads();
            storeA_regs(ar, sm, (s ^ 1) * 16384, t);
            CP_WAIT0();
            __syncthreads();
        }
    }

    // fused epilogue from fragments
    #pragma unroll
    for (int mf = 0; mf < 2; mf++)
        #pragma unroll
        for (int nf = 0; nf < 8; nf++) {
            int r = wm * 32 + mf * 16 + (lane >> 2);
            int c = wn * 64 + nf * 8 + 2 * (lane & 3);
            size_t g0 = ((size_t)b * NNODE + n0 + r) * FEAT + c;
            float2 lv0 = *reinterpret_cast<const float2*>(g_l2 + g0);
            *reinterpret_cast<float2*>(out + g0) =
                make_float2(tanhf(acc[mf][nf][0] + lv0.x), tanhf(acc[mf][nf][1] + lv0.y));
            size_t g1 = g0 + (size_t)8 * FEAT;
            float2 lv1 = *reinterpret_cast<const float2*>(g_l2 + g1);
            *reinterpret_cast<float2*>(out + g1) =
                make_float2(tanhf(acc[mf][nf][2] + lv1.x), tanhf(acc[mf][nf][3] + lv1.y));
        }
}

// ---------------- launch ----------------
extern "C" void kernel_launch(void* const* d_in, const int* in_sizes, int n_in,
                              void* d_out, int out_size)
{
    const float* n_tensor   = (const float*)d_in[0];
    const float* adj_tensor = (const float*)d_in[1];
    const float* W_adj      = (const float*)d_in[2];
    const float* b_adj      = (const float*)d_in[3];
    const float* W2         = (const float*)d_in[4];
    const float* b2         = (const float*)d_in[5];
    float* out = (float*)d_out;

    cudaFuncSetAttribute(k_lin, cudaFuncAttributeMaxDynamicSharedMemorySize, LIN_SMEM);
    cudaFuncSetAttribute(k_mp,  cudaFuncAttributeMaxDynamicSharedMemorySize, MP_SMEM);

    k_split_w<<<5, 256>>>(W_adj, W2);

    dim3 g1((BATCH * NNODE) / 128, 5);
    k_lin<<<g1, 256, LIN_SMEM>>>(n_tensor, b_adj, b2);

    k_mp<<<BATCH * 4, 256, MP_SMEM>>>(adj_tensor, out);
}

// round 5
// speedup vs baseline: 3.5942x; 1.7568x over previous
#include <cuda_runtime.h>
#include <cuda_bf16.h>
#include <cstdint>
#include <math.h>

#define BATCH 256
#define NNODE 512
#define FEAT  128
#define NE    4

// ---------------- scratch (static device allocs allowed) ----------------
__device__ __nv_bfloat16 g_wh[5 * FEAT * FEAT];                   // W hi [e][k][u]
__device__ __nv_bfloat16 g_wl[5 * FEAT * FEAT];                   // W lo
__device__ __nv_bfloat16 g_hh[(size_t)BATCH * NE * NNODE * FEAT]; // h hi [b][e][m][u]
__device__ __nv_bfloat16 g_hl[(size_t)BATCH * NE * NNODE * FEAT]; // h lo
__device__ float         g_l2[(size_t)BATCH * NNODE * FEAT];      // n@W2+b2 [row][u]

// ---------------- helpers ----------------
__device__ __forceinline__ uint32_t smem_u32(const void* p) {
    uint32_t a;
    asm("{ .reg .u64 t; cvta.to.shared.u64 t, %1; cvt.u32.u64 %0, t; }" : "=r"(a) : "l"(p));
    return a;
}
#define SWZ(x)    ((x) ^ (((x) >> 3) & 0x70))   // 128B rows
#define SWZ256(x) ((x) ^ (((x) >> 4) & 0x70))   // 256B rows

__device__ __forceinline__ void split2(float a, float b, uint32_t& hh, uint32_t& ll) {
    __nv_bfloat162 h = __floats2bfloat162_rn(a, b);
    float ra = a - __low2float(h);
    float rb = b - __high2float(h);
    hh = *reinterpret_cast<uint32_t*>(&h);
    __nv_bfloat162 l = __floats2bfloat162_rn(ra, rb);
    ll = *reinterpret_cast<uint32_t*>(&l);
}

__device__ __forceinline__ void ldm4(uint32_t a[4], uint32_t adr) {
    asm volatile("ldmatrix.sync.aligned.m8n8.x4.shared.b16 {%0,%1,%2,%3}, [%4];"
        : "=r"(a[0]), "=r"(a[1]), "=r"(a[2]), "=r"(a[3]) : "r"(adr));
}
__device__ __forceinline__ void ldm4t(uint32_t a[4], uint32_t adr) {
    asm volatile("ldmatrix.sync.aligned.m8n8.x4.trans.shared.b16 {%0,%1,%2,%3}, [%4];"
        : "=r"(a[0]), "=r"(a[1]), "=r"(a[2]), "=r"(a[3]) : "r"(adr));
}
__device__ __forceinline__ void mma_bf(float c[4], const uint32_t a[4],
                                       uint32_t b0, uint32_t b1) {
    asm volatile("mma.sync.aligned.m16n8k16.row.col.f32.bf16.bf16.f32 "
        "{%0,%1,%2,%3}, {%4,%5,%6,%7}, {%8,%9}, {%0,%1,%2,%3};"
        : "+f"(c[0]), "+f"(c[1]), "+f"(c[2]), "+f"(c[3])
        : "r"(a[0]), "r"(a[1]), "r"(a[2]), "r"(a[3]), "r"(b0), "r"(b1));
}
#define CP_COMMIT() asm volatile("cp.async.commit_group;" ::: "memory")
#define CP_WAIT0()  asm volatile("cp.async.wait_group 0;" ::: "memory")
#define CPA16(dst, src) asm volatile("cp.async.cg.shared.global [%0], [%1], 16;" \
                                     :: "r"(dst), "l"(src) : "memory")

// ---- A tile: 128 rows x 128B [hi 64B | lo 64B], swizzled (per 32-k slab) ----
struct ARaw { float4 v[4]; };
__device__ __forceinline__ void loadA_raw(ARaw& a, const float* __restrict__ g, int rs, int t) {
    int r = t >> 1, c0 = (t & 1) * 16;
    const float* src = g + (size_t)r * rs + c0;
    #pragma unroll
    for (int j = 0; j < 4; j++) a.v[j] = *reinterpret_cast<const float4*>(src + 4 * j);
}
__device__ __forceinline__ void storeA_split(const ARaw& a, char* sm, int base, int t) {
    int r = t >> 1, c0 = (t & 1) * 16;
    #pragma unroll
    for (int j = 0; j < 4; j++) {
        uint32_t h0, l0, h1, l1;
        split2(a.v[j].x, a.v[j].y, h0, l0);
        split2(a.v[j].z, a.v[j].w, h1, l1);
        int col = c0 + 4 * j;
        *reinterpret_cast<uint2*>(sm + base + SWZ(r * 128 + col * 2)) = make_uint2(h0, h1);
        *reinterpret_cast<uint2*>(sm + base + SWZ(r * 128 + 64 + col * 2)) = make_uint2(l0, l1);
    }
}

// ---- B tile: rows of 256B (128 u bf16), hi plane then lo plane, SWZ256 ----
// rows32: [32 k rows][128 u] per plane (k_mp stage)
__device__ __forceinline__ void loadB32_async(uint32_t sb, int base,
                                              const __nv_bfloat16* __restrict__ gh,
                                              const __nv_bfloat16* __restrict__ gl, int t) {
    #pragma unroll
    for (int j = 0; j < 4; j++) {
        int c = t + 256 * j;
        int p = c >> 9, kr = (c >> 4) & 31, ch = c & 15;
        const __nv_bfloat16* src = (p ? gl : gh) + (size_t)kr * FEAT + ch * 8;
        uint32_t dst = sb + base + p * 8192 + SWZ256(kr * 256 + ch * 16);
        CPA16(dst, src);
    }
}
// rows128: [128 k rows][128 u] per plane (k_lin W tile)
__device__ __forceinline__ void loadB128_async(uint32_t sb, int base,
                                               const __nv_bfloat16* __restrict__ gh,
                                               const __nv_bfloat16* __restrict__ gl, int t) {
    #pragma unroll
    for (int j = 0; j < 8; j++) {
        int c = t + 256 * j;
        int kr = c >> 4, ch = c & 15;
        CPA16(sb + base + SWZ256(kr * 256 + ch * 16), gh + (size_t)kr * FEAT + ch * 8);
        CPA16(sb + base + 32768 + SWZ256(kr * 256 + ch * 16), gl + (size_t)kr * FEAT + ch * 8);
    }
}

// ---- compute one 32-k stage ----
// offA: A sub-tile base (128B rows). offB: hi-plane base; lo at offB+pstride.
// kbase: k row offset inside the B planes.
__device__ __forceinline__ void compute_stage(uint32_t sb, int offA, int offB,
                                              int kbase, int pstride,
                                              int wm, int wn, int lane,
                                              float acc[2][8][4]) {
    #pragma unroll
    for (int ks = 0; ks < 2; ks++) {
        uint32_t Ah[2][4], Al[2][4];
        #pragma unroll
        for (int mf = 0; mf < 2; mf++) {
            int row = wm * 32 + mf * 16 + (lane & 15);
            int kk  = ks * 16 + ((lane >> 4) * 8);
            ldm4(Ah[mf], sb + offA + SWZ(row * 128 + kk * 2));
            ldm4(Al[mf], sb + offA + SWZ(row * 128 + 64 + kk * 2));
        }
        int krow  = kbase + ks * 16 + ((lane >> 3) & 1) * 8 + (lane & 7);
        int cbase = wn * 8 + (lane >> 4);
        #pragma unroll
        for (int nfp = 0; nfp < 4; nfp++) {
            uint32_t bofs = SWZ256(krow * 256 + (cbase + nfp * 2) * 16);
            uint32_t BH[4], BL[4];
            ldm4t(BH, sb + offB + bofs);
            ldm4t(BL, sb + offB + pstride + bofs);
            int n0 = nfp * 2, n1 = nfp * 2 + 1;
            mma_bf(acc[0][n0], Ah[0], BH[0], BH[1]);
            mma_bf(acc[1][n0], Ah[1], BH[0], BH[1]);
            mma_bf(acc[0][n0], Ah[0], BL[0], BL[1]);
            mma_bf(acc[1][n0], Ah[1], BL[0], BL[1]);
            mma_bf(acc[0][n0], Al[0], BH[0], BH[1]);
            mma_bf(acc[1][n0], Al[1], BH[0], BH[1]);
            mma_bf(acc[0][n1], Ah[0], BH[2], BH[3]);
            mma_bf(acc[1][n1], Ah[1], BH[2], BH[3]);
            mma_bf(acc[0][n1], Ah[0], BL[2], BL[3]);
            mma_bf(acc[1][n1], Ah[1], BL[2], BL[3]);
            mma_bf(acc[0][n1], Al[0], BH[2], BH[3]);
            mma_bf(acc[1][n1], Al[1], BH[2], BH[3]);
        }
    }
}

// ---------------- pre-kernel: split W (layout-preserving, fully parallel) ----------------
__global__ __launch_bounds__(256) void k_split_w(const float* __restrict__ Wadj,
                                                 const float* __restrict__ W2) {
    int idx4 = blockIdx.x * 256 + threadIdx.x;        // float4 index over [5][16384]
    int e = idx4 >> 12;
    const float* src = (e < NE) ? (Wadj + (size_t)idx4 * 4)
                                : (W2 + ((size_t)idx4 - 4 * 4096) * 4);
    float4 v = *reinterpret_cast<const float4*>(src);
    uint32_t h0, l0, h1, l1;
    split2(v.x, v.y, h0, l0);
    split2(v.z, v.w, h1, l1);
    *reinterpret_cast<uint2*>(g_wh + (size_t)idx4 * 4) = make_uint2(h0, h1);
    *reinterpret_cast<uint2*>(g_wl + (size_t)idx4 * 4) = make_uint2(l0, l1);
}

// ---------------- k_lin: h_e = n @ W_e + b_e, loop e in-block ----------------
// smem: A 4 sub-tiles @ st*16384 (64KB); B double buf @ 65536 + buf*65536 (128KB).
#define LIN_SMEM 196608
__global__ __launch_bounds__(256, 1) void k_lin(const float* __restrict__ nt,
                                                const float* __restrict__ badj,
                                                const float* __restrict__ b2) {
    extern __shared__ char sm[];
    uint32_t sb = smem_u32(sm);
    int t = threadIdx.x, lane = t & 31, w = t >> 5;
    int wm = w >> 1, wn = w & 1;
    int r0 = blockIdx.x * 128;
    int b = r0 >> 9, m0 = r0 & 511;

    // prefetch W(e=0) + load/split A tile
    loadB128_async(sb, 65536, g_wh, g_wl, t);
    CP_COMMIT();
    #pragma unroll
    for (int st = 0; st < 4; st++) {
        ARaw a;
        loadA_raw(a, nt + (size_t)r0 * FEAT + st * 32, FEAT, t);
        storeA_split(a, sm, st * 16384, t);
    }
    CP_WAIT0();
    __syncthreads();

    #pragma unroll 1
    for (int e = 0; e <= NE; e++) {
        int buf = e & 1;
        if (e < NE) {
            loadB128_async(sb, 65536 + (buf ^ 1) * 65536,
                           g_wh + (size_t)(e + 1) * FEAT * FEAT,
                           g_wl + (size_t)(e + 1) * FEAT * FEAT, t);
            CP_COMMIT();
        }

        float acc[2][8][4];
        #pragma unroll
        for (int i = 0; i < 2; i++)
            #pragma unroll
            for (int j = 0; j < 8; j++)
                #pragma unroll
                for (int q = 0; q < 4; q++) acc[i][j][q] = 0.f;

        #pragma unroll
        for (int st = 0; st < 4; st++)
            compute_stage(sb, st * 16384, 65536 + buf * 65536, st * 32, 32768,
                          wm, wn, lane, acc);

        const float* bias = (e < NE) ? (badj + e * FEAT) : b2;
        #pragma unroll
        for (int mf = 0; mf < 2; mf++)
            #pragma unroll
            for (int nf = 0; nf < 8; nf++) {
                int r = wm * 32 + mf * 16 + (lane >> 2);
                int c = wn * 64 + nf * 8 + 2 * (lane & 3);
                float2 bv = *reinterpret_cast<const float2*>(bias + c);
                float h0 = acc[mf][nf][0] + bv.x, h1 = acc[mf][nf][1] + bv.y;
                float h2 = acc[mf][nf][2] + bv.x, h3 = acc[mf][nf][3] + bv.y;
                if (e < NE) {
                    size_t g0 = ((size_t)(b * NE + e) * NNODE + m0 + r) * FEAT + c;
                    size_t g1 = g0 + (size_t)8 * FEAT;
                    uint32_t hh, ll;
                    split2(h0, h1, hh, ll);
                    *reinterpret_cast<uint32_t*>(g_hh + g0) = hh;
                    *reinterpret_cast<uint32_t*>(g_hl + g0) = ll;
                    split2(h2, h3, hh, ll);
                    *reinterpret_cast<uint32_t*>(g_hh + g1) = hh;
                    *reinterpret_cast<uint32_t*>(g_hl + g1) = ll;
                } else {
                    size_t g0 = (size_t)(r0 + r) * FEAT + c;
                    *reinterpret_cast<float2*>(g_l2 + g0) = make_float2(h0, h1);
                    *reinterpret_cast<float2*>(g_l2 + g0 + (size_t)8 * FEAT) =
                        make_float2(h2, h3);
                }
            }
        if (e < NE) {
            CP_WAIT0();
            __syncthreads();
        }
    }
}

// ---------------- k_mp: out = tanh(sum_e adj_e @ h_e + lin2) ----------------
// smem: A bufs @ s*16384 (32KB); B bufs @ 32768 + s*16384 (hi 8KB | lo 8KB). 64KB.
#define MP_SMEM 65536
__global__ __launch_bounds__(256, 1) void k_mp(const float* __restrict__ adj,
                                               float* __restrict__ out) {
    extern __shared__ char sm[];
    uint32_t sb = smem_u32(sm);
    int t = threadIdx.x, lane = t & 31, w = t >> 5;
    int wm = w >> 1, wn = w & 1;
    int b = blockIdx.x >> 2, n0 = (blockIdx.x & 3) * 128;

    float acc[2][8][4];
    #pragma unroll
    for (int i = 0; i < 2; i++)
        #pragma unroll
        for (int j = 0; j < 8; j++)
            #pragma unroll
            for (int q = 0; q < 4; q++) acc[i][j][q] = 0.f;

    ARaw ar;
    // chunk i: e = i>>4, k0 = (i&15)*32
    {
        const float* Ap = adj + ((size_t)(b * NE) * NNODE + n0) * NNODE;
        loadA_raw(ar, Ap, NNODE, t);
        size_t hb = (size_t)(b * NE) * NNODE * FEAT;
        loadB32_async(sb, 32768, g_hh + hb, g_hl + hb, t);
        CP_COMMIT();
        storeA_split(ar, sm, 0, t);
        CP_WAIT0();
        __syncthreads();
    }

    #pragma unroll 1
    for (int i = 0; i < 64; i++) {
        int s = i & 1;
        if (i < 63) {
            int e = (i + 1) >> 4, k0 = ((i + 1) & 15) * 32;
            const float* Ap = adj + ((size_t)(b * NE + e) * NNODE + n0) * NNODE + k0;
            loadA_raw(ar, Ap, NNODE, t);   // LDGs issued; split deferred past compute
            size_t hb = ((size_t)(b * NE + e) * NNODE + k0) * FEAT;
            loadB32_async(sb, 32768 + (s ^ 1) * 16384, g_hh + hb, g_hl + hb, t);
            CP_COMMIT();
        }
        compute_stage(sb, s * 16384, 32768 + s * 16384, 0, 8192, wm, wn, lane, acc);
        if (i < 63) {
            __syncthreads();
            storeA_split(ar, sm, (s ^ 1) * 16384, t);
            CP_WAIT0();
            __syncthreads();
        }
    }

    // fused epilogue from fragments
    #pragma unroll
    for (int mf = 0; mf < 2; mf++)
        #pragma unroll
        for (int nf = 0; nf < 8; nf++) {
            int r = wm * 32 + mf * 16 + (lane >> 2);
            int c = wn * 64 + nf * 8 + 2 * (lane & 3);
            size_t g0 = ((size_t)b * NNODE + n0 + r) * FEAT + c;
            float2 lv0 = *reinterpret_cast<const float2*>(g_l2 + g0);
            *reinterpret_cast<float2*>(out + g0) =
                make_float2(tanhf(acc[mf][nf][0] + lv0.x), tanhf(acc[mf][nf][1] + lv0.y));
            size_t g1 = g0 + (size_t)8 * FEAT;
            float2 lv1 = *reinterpret_cast<const float2*>(g_l2 + g1);
            *reinterpret_cast<float2*>(out + g1) =
                make_float2(tanhf(acc[mf][nf][2] + lv1.x), tanhf(acc[mf][nf][3] + lv1.y));
        }
}

// ---------------- launch ----------------
extern "C" void kernel_launch(void* const* d_in, const int* in_sizes, int n_in,
                              void* d_out, int out_size)
{
    const float* n_tensor   = (const float*)d_in[0];
    const float* adj_tensor = (const float*)d_in[1];
    const float* W_adj      = (const float*)d_in[2];
    const float* b_adj      = (const float*)d_in[3];
    const float* W2         = (const float*)d_in[4];
    const float* b2         = (const float*)d_in[5];
    float* out = (float*)d_out;

    cudaFuncSetAttribute(k_lin, cudaFuncAttributeMaxDynamicSharedMemorySize, LIN_SMEM);
    cudaFuncSetAttribute(k_mp,  cudaFuncAttributeMaxDynamicSharedMemorySize, MP_SMEM);

    k_split_w<<<80, 256>>>(W_adj, W2);                       // 5*16384/4/256 = 80
    k_lin<<<(BATCH * NNODE) / 128, 256, LIN_SMEM>>>(n_tensor, b_adj, b2);
    k_mp<<<BATCH * 4, 256, MP_SMEM>>>(adj_tensor, out);
}